// round 9
// baseline (speedup 1.0000x reference)
#include <cuda_runtime.h>
#include <cstdint>

#define THREADS 256

// Packed fp32x2 FMA (Blackwell FFMA2) — only reachable via PTX.
static __device__ __forceinline__ void fma2(unsigned long long& d,
                                            unsigned long long a,
                                            unsigned long long b) {
    asm("fma.rn.f32x2 %0, %1, %2, %0;" : "+l"(d) : "l"(a), "l"(b));
}

__global__ __launch_bounds__(THREADS, 1)
void lab_fused_kernel(const float* __restrict__ x,
                      const float* __restrict__ w_in,
                      const float* __restrict__ b_in,
                      const float* __restrict__ w_out,
                      const float* __restrict__ b_out,
                      const float* __restrict__ gamma,
                      const float* __restrict__ beta,
                      float* __restrict__ out)
{
    constexpr int C   = 256;
    constexpr int SXS = 260;   // stride of sx/so rows (mult of 4 -> 16B aligned float4)
    constexpr int QS  = 33;    // stride of q/k/v rows
    constexpr int SSS = 66;    // stride of score rows
    const float SCALE = 0.17677669529663687f;   // 1/sqrt(32)

    extern __shared__ float sm[];
    float* sx  = sm;                    // 64*260  input tile, later proj result
    float* so  = sx + 64*SXS;           // 64*260  attention output, later LN result
    float* wsm = so + 64*SXS;           // 128*64  swizzled weight K-tile
    float* sq  = wsm + 128*64;          // 64*33
    float* sk  = sq + 64*QS;            // 64*33
    float* sv  = sk + 64*QS;            // 64*33
    float* sS  = sv + 64*QS;            // 64*66  scores / probs

    const int tid = threadIdx.x;
    const int n   = blockIdx.x;
    const int bb  = n >> 10;
    const int hn  = (n >> 5) & 31;
    const int wn  = n & 31;

    // ---------------- load x window: [64 tokens][256 ch] ----------------
    const float* xw = x + (size_t)bb * C * 65536 + (size_t)(hn * 8) * 256 + wn * 8;
    for (int idx = tid; idx < 64 * C; idx += THREADS) {
        int c = idx >> 6, t = idx & 63;
        sx[t * SXS + c] = xw[(size_t)c * 65536 + (t >> 3) * 256 + (t & 7)];
    }
    __syncthreads();

    const int ty   = tid >> 4;
    const int tx   = tid & 15;
    const int typ  = ty >> 1;                 // token group: tokens typ*8 + i (warp-uniform!)
    const int colg = tx + ((ty & 1) << 4);    // 0..31 column group

    // ---------------- per head: QKV GEMM + attention ----------------
    for (int h = 0; h < 8; ++h) {
        unsigned long long acc[8][3];
        #pragma unroll
        for (int i = 0; i < 8; ++i) {
            #pragma unroll
            for (int j = 0; j < 3; ++j) acc[i][j] = 0ull;
        }

        for (int kt = 0; kt < 4; ++kt) {
            const int kb = kt << 6;
            // stage w_in K-tile: 96 rows (q32|k32|v32 of head h) x 64 k, XOR-swizzled
            #pragma unroll
            for (int l = 0; l < 24; ++l) {
                int idx = tid + l * THREADS;
                int r = idx >> 6, kc = idx & 63;
                int e = (r < 32) ? (h * 32 + r)
                      : (r < 64) ? (256 + h * 32 + r - 32)
                                 : (512 + h * 32 + r - 64);
                wsm[(r << 6) + ((((kc >> 2) ^ (r & 15)) << 2) | (kc & 3))] =
                    w_in[e * C + kb + kc];
            }
            __syncthreads();

            #pragma unroll 4
            for (int kk = 0; kk < 64; kk += 4) {
                ulonglong2 a[8];
                #pragma unroll
                for (int i = 0; i < 8; ++i)
                    a[i] = *(const ulonglong2*)(sx + (typ * 8 + i) * SXS + kb + kk);
                const int sw = ((kk >> 2) ^ tx) << 2;
                ulonglong2 bv[3];
                #pragma unroll
                for (int j = 0; j < 3; ++j)
                    bv[j] = *(const ulonglong2*)(wsm + ((colg + 32 * j) << 6) + sw);
                #pragma unroll
                for (int i = 0; i < 8; ++i) {
                    #pragma unroll
                    for (int j = 0; j < 3; ++j) {
                        fma2(acc[i][j], a[i].x, bv[j].x);
                        fma2(acc[i][j], a[i].y, bv[j].y);
                    }
                }
            }
            __syncthreads();
        }

        // epilogue: reduce packed pairs, add bias, scatter to q/k/v
        #pragma unroll
        for (int j = 0; j < 3; ++j) {
            const int col = colg + 32 * j;          // 0..95
            float* dst; int d, e;
            if (j == 0)      { dst = sq; d = col;       e = h * 32 + d; }
            else if (j == 1) { dst = sk; d = col - 32;  e = 256 + h * 32 + d; }
            else             { dst = sv; d = col - 64;  e = 512 + h * 32 + d; }
            const float bias = b_in[e];
            #pragma unroll
            for (int i = 0; i < 8; ++i) {
                unsigned long long A = acc[i][j];
                float lo = __uint_as_float((unsigned)A);
                float hi = __uint_as_float((unsigned)(A >> 32));
                dst[(typ * 8 + i) * QS + d] = lo + hi + bias;
            }
        }
        __syncthreads();

        // scores: S[qt][kt] = q . k   (scale folded into softmax)
        {
            float f[4][4];
            #pragma unroll
            for (int i = 0; i < 4; ++i) {
                #pragma unroll
                for (int j = 0; j < 4; ++j) f[i][j] = 0.f;
            }
            #pragma unroll 4
            for (int d = 0; d < 32; ++d) {
                float av[4], bv2[4];
                #pragma unroll
                for (int i = 0; i < 4; ++i) av[i] = sq[(ty * 4 + i) * QS + d];
                #pragma unroll
                for (int j = 0; j < 4; ++j) bv2[j] = sk[(tx + 16 * j) * QS + d];
                #pragma unroll
                for (int i = 0; i < 4; ++i) {
                    #pragma unroll
                    for (int j = 0; j < 4; ++j) f[i][j] = fmaf(av[i], bv2[j], f[i][j]);
                }
            }
            #pragma unroll
            for (int i = 0; i < 4; ++i) {
                #pragma unroll
                for (int j = 0; j < 4; ++j)
                    sS[(ty * 4 + i) * SSS + tx + 16 * j] = f[i][j];
            }
        }
        __syncthreads();

        // softmax over k dim (scale applied here; exact softmax(scale*s))
        {
            const int wid = tid >> 5, lane = tid & 31;
            #pragma unroll
            for (int r = 0; r < 8; ++r) {
                const int t = wid * 8 + r;
                float v0 = sS[t * SSS + lane];
                float v1 = sS[t * SSS + 32 + lane];
                float m = fmaxf(v0, v1);
                #pragma unroll
                for (int o = 16; o > 0; o >>= 1)
                    m = fmaxf(m, __shfl_xor_sync(0xffffffffu, m, o));
                float e0 = __expf((v0 - m) * SCALE);
                float e1 = __expf((v1 - m) * SCALE);
                float s = e0 + e1;
                #pragma unroll
                for (int o = 16; o > 0; o >>= 1)
                    s += __shfl_xor_sync(0xffffffffu, s, o);
                const float inv = 1.0f / s;
                sS[t * SSS + lane]      = e0 * inv;
                sS[t * SSS + 32 + lane] = e1 * inv;
            }
        }
        __syncthreads();

        // o_h = P @ V  -> so[:, h*32 : h*32+32]
        {
            float f[4][2];
            #pragma unroll
            for (int i = 0; i < 4; ++i) { f[i][0] = 0.f; f[i][1] = 0.f; }
            #pragma unroll 4
            for (int k2 = 0; k2 < 64; ++k2) {
                float av[4];
                #pragma unroll
                for (int i = 0; i < 4; ++i) av[i] = sS[(ty * 4 + i) * SSS + k2];
                const float b0 = sv[k2 * QS + tx];
                const float b1 = sv[k2 * QS + tx + 16];
                #pragma unroll
                for (int i = 0; i < 4; ++i) {
                    f[i][0] = fmaf(av[i], b0, f[i][0]);
                    f[i][1] = fmaf(av[i], b1, f[i][1]);
                }
            }
            #pragma unroll
            for (int i = 0; i < 4; ++i) {
                so[(ty * 4 + i) * SXS + h * 32 + tx]      = f[i][0];
                so[(ty * 4 + i) * SXS + h * 32 + 16 + tx] = f[i][1];
            }
        }
        __syncthreads();
    }

    // ---------------- out projection: sx = so @ w_out^T + b_out ----------------
    for (int half = 0; half < 2; ++half) {
        const int co0 = half << 7;
        unsigned long long acc[8][4];
        #pragma unroll
        for (int i = 0; i < 8; ++i) {
            #pragma unroll
            for (int j = 0; j < 4; ++j) acc[i][j] = 0ull;
        }

        for (int kt = 0; kt < 4; ++kt) {
            const int kb = kt << 6;
            #pragma unroll
            for (int l = 0; l < 32; ++l) {
                int idx = tid + l * THREADS;
                int r = idx >> 6, kc = idx & 63;
                wsm[(r << 6) + ((((kc >> 2) ^ (r & 15)) << 2) | (kc & 3))] =
                    w_out[(co0 + r) * C + kb + kc];
            }
            __syncthreads();

            #pragma unroll 4
            for (int kk = 0; kk < 64; kk += 4) {
                ulonglong2 a[8];
                #pragma unroll
                for (int i = 0; i < 8; ++i)
                    a[i] = *(const ulonglong2*)(so + (typ * 8 + i) * SXS + kb + kk);
                const int sw = ((kk >> 2) ^ tx) << 2;
                ulonglong2 bv[4];
                #pragma unroll
                for (int j = 0; j < 4; ++j)
                    bv[j] = *(const ulonglong2*)(wsm + ((colg + 32 * j) << 6) + sw);
                #pragma unroll
                for (int i = 0; i < 8; ++i) {
                    #pragma unroll
                    for (int j = 0; j < 4; ++j) {
                        fma2(acc[i][j], a[i].x, bv[j].x);
                        fma2(acc[i][j], a[i].y, bv[j].y);
                    }
                }
            }
            __syncthreads();
        }

        #pragma unroll
        for (int j = 0; j < 4; ++j) {
            const int col = co0 + colg + 32 * j;
            const float bias = b_out[col];
            #pragma unroll
            for (int i = 0; i < 8; ++i) {
                unsigned long long A = acc[i][j];
                float lo = __uint_as_float((unsigned)A);
                float hi = __uint_as_float((unsigned)(A >> 32));
                sx[(typ * 8 + i) * SXS + col] = lo + hi + bias;
            }
        }
        __syncthreads();
    }

    // ---------------- LayerNorm over channels (per token) ----------------
    {
        const int wid = tid >> 5, lane = tid & 31;
        for (int r = 0; r < 8; ++r) {
            const int t = wid * 8 + r;
            float v[8];
            #pragma unroll
            for (int j = 0; j < 8; ++j) v[j] = sx[t * SXS + j * 32 + lane];
            float s = 0.f;
            #pragma unroll
            for (int j = 0; j < 8; ++j) s += v[j];
            #pragma unroll
            for (int o = 16; o > 0; o >>= 1) s += __shfl_xor_sync(0xffffffffu, s, o);
            const float mu = s * (1.0f / 256.0f);
            float q2 = 0.f;
            #pragma unroll
            for (int j = 0; j < 8; ++j) { float d = v[j] - mu; q2 = fmaf(d, d, q2); }
            #pragma unroll
            for (int o = 16; o > 0; o >>= 1) q2 += __shfl_xor_sync(0xffffffffu, q2, o);
            const float rs = rsqrtf(q2 * (1.0f / 256.0f) + 1e-5f);
            #pragma unroll
            for (int j = 0; j < 8; ++j) {
                const int c = j * 32 + lane;
                so[t * SXS + c] = (v[j] - mu) * rs * gamma[c] + beta[c];
            }
        }
    }
    __syncthreads();

    // ---------------- scatter to NCHW output ----------------
    float* ow = out + (size_t)bb * C * 65536 + (size_t)(hn * 8) * 256 + wn * 8;
    for (int idx = tid; idx < 64 * C; idx += THREADS) {
        int c = idx >> 6, t = idx & 63;
        ow[(size_t)c * 65536 + (t >> 3) * 256 + (t & 7)] = so[t * SXS + c];
    }
}

extern "C" void kernel_launch(void* const* d_in, const int* in_sizes, int n_in,
                              void* d_out, int out_size) {
    (void)in_sizes; (void)n_in; (void)out_size;
    const float* x     = (const float*)d_in[0];
    const float* w_in  = (const float*)d_in[1];
    const float* b_in  = (const float*)d_in[2];
    const float* w_out = (const float*)d_in[3];
    const float* b_out = (const float*)d_in[4];
    const float* gamma = (const float*)d_in[5];
    const float* beta  = (const float*)d_in[6];
    float* out = (float*)d_out;

    const int smem_bytes = (64 * 260 * 2 + 128 * 64 + 3 * 64 * 33 + 64 * 66) * 4; // 208128
    cudaFuncSetAttribute(lab_fused_kernel,
                         cudaFuncAttributeMaxDynamicSharedMemorySize, smem_bytes);
    lab_fused_kernel<<<4096, THREADS, smem_bytes>>>(x, w_in, b_in, w_out, b_out,
                                                    gamma, beta, out);
}

// round 10
// speedup vs baseline: 1.0053x; 1.0053x over previous
#include <cuda_runtime.h>
#include <cstdint>

#define THREADS 256

// Packed fp32x2 FMA (Blackwell FFMA2) — only reachable via PTX.
static __device__ __forceinline__ void fma2(unsigned long long& d,
                                            unsigned long long a,
                                            unsigned long long b) {
    asm("fma.rn.f32x2 %0, %1, %2, %0;" : "+l"(d) : "l"(a), "l"(b));
}

__global__ __launch_bounds__(THREADS, 1)
void lab_fused_kernel(const float* __restrict__ x,
                      const float* __restrict__ w_in,
                      const float* __restrict__ b_in,
                      const float* __restrict__ w_out,
                      const float* __restrict__ b_out,
                      const float* __restrict__ gamma,
                      const float* __restrict__ beta,
                      float* __restrict__ out)
{
    constexpr int C   = 256;
    constexpr int SXS = 260;   // stride of sx/so rows (mult of 4 -> 16B aligned float4)
    constexpr int QS  = 33;    // stride of q/k/v rows
    constexpr int SSS = 66;    // stride of score rows
    const float SCALE = 0.17677669529663687f;   // 1/sqrt(32)

    extern __shared__ float sm[];
    float* sx  = sm;                    // 64*260  input tile, later proj result
    float* so  = sx + 64*SXS;           // 64*260  attention output, later LN result
    float* wsm = so + 64*SXS;           // 128*64  swizzled weight K-tile
    float* sq  = wsm + 128*64;          // 64*33
    float* sk  = sq + 64*QS;            // 64*33
    float* sv  = sk + 64*QS;            // 64*33
    float* sS  = sv + 64*QS;            // 64*66  scores / probs

    const int tid = threadIdx.x;
    const int n   = blockIdx.x;
    const int bb  = n >> 10;
    const int hn  = (n >> 5) & 31;
    const int wn  = n & 31;

    // ---------------- load x window: [64 tokens][256 ch] ----------------
    const float* xw = x + (size_t)bb * C * 65536 + (size_t)(hn * 8) * 256 + wn * 8;
    for (int idx = tid; idx < 64 * C; idx += THREADS) {
        int c = idx >> 6, t = idx & 63;
        sx[t * SXS + c] = xw[(size_t)c * 65536 + (t >> 3) * 256 + (t & 7)];
    }
    __syncthreads();

    const int ty   = tid >> 4;
    const int tx   = tid & 15;
    const int typ  = ty >> 1;                 // token group: tokens typ*8 + i (warp-uniform!)
    const int colg = tx + ((ty & 1) << 4);    // 0..31 column group

    // ---------------- per head: QKV GEMM + attention ----------------
    for (int h = 0; h < 8; ++h) {
        unsigned long long acc[8][3];
        #pragma unroll
        for (int i = 0; i < 8; ++i) {
            #pragma unroll
            for (int j = 0; j < 3; ++j) acc[i][j] = 0ull;
        }

        for (int kt = 0; kt < 4; ++kt) {
            const int kb = kt << 6;
            // stage w_in K-tile: 96 rows (q32|k32|v32 of head h) x 64 k, XOR-swizzled
            #pragma unroll
            for (int l = 0; l < 24; ++l) {
                int idx = tid + l * THREADS;
                int r = idx >> 6, kc = idx & 63;
                int e = (r < 32) ? (h * 32 + r)
                      : (r < 64) ? (256 + h * 32 + r - 32)
                                 : (512 + h * 32 + r - 64);
                wsm[(r << 6) + ((((kc >> 2) ^ (r & 15)) << 2) | (kc & 3))] =
                    w_in[e * C + kb + kc];
            }
            __syncthreads();

            #pragma unroll 4
            for (int kk = 0; kk < 64; kk += 4) {
                ulonglong2 a[8];
                #pragma unroll
                for (int i = 0; i < 8; ++i)
                    a[i] = *(const ulonglong2*)(sx + (typ * 8 + i) * SXS + kb + kk);
                const int sw = ((kk >> 2) ^ tx) << 2;
                ulonglong2 bv[3];
                #pragma unroll
                for (int j = 0; j < 3; ++j)
                    bv[j] = *(const ulonglong2*)(wsm + ((colg + 32 * j) << 6) + sw);
                #pragma unroll
                for (int i = 0; i < 8; ++i) {
                    #pragma unroll
                    for (int j = 0; j < 3; ++j) {
                        fma2(acc[i][j], a[i].x, bv[j].x);
                        fma2(acc[i][j], a[i].y, bv[j].y);
                    }
                }
            }
            __syncthreads();
        }

        // epilogue: reduce packed pairs, add bias, scatter to q/k/v
        #pragma unroll
        for (int j = 0; j < 3; ++j) {
            const int col = colg + 32 * j;          // 0..95
            float* dst; int d, e;
            if (j == 0)      { dst = sq; d = col;       e = h * 32 + d; }
            else if (j == 1) { dst = sk; d = col - 32;  e = 256 + h * 32 + d; }
            else             { dst = sv; d = col - 64;  e = 512 + h * 32 + d; }
            const float bias = b_in[e];
            #pragma unroll
            for (int i = 0; i < 8; ++i) {
                unsigned long long A = acc[i][j];
                float lo = __uint_as_float((unsigned)A);
                float hi = __uint_as_float((unsigned)(A >> 32));
                dst[(typ * 8 + i) * QS + d] = lo + hi + bias;
            }
        }
        __syncthreads();

        // scores: S[qt][kt] = q . k   (scale folded into softmax)
        {
            float f[4][4];
            #pragma unroll
            for (int i = 0; i < 4; ++i) {
                #pragma unroll
                for (int j = 0; j < 4; ++j) f[i][j] = 0.f;
            }
            #pragma unroll 4
            for (int d = 0; d < 32; ++d) {
                float av[4], bv2[4];
                #pragma unroll
                for (int i = 0; i < 4; ++i) av[i] = sq[(ty * 4 + i) * QS + d];
                #pragma unroll
                for (int j = 0; j < 4; ++j) bv2[j] = sk[(tx + 16 * j) * QS + d];
                #pragma unroll
                for (int i = 0; i < 4; ++i) {
                    #pragma unroll
                    for (int j = 0; j < 4; ++j) f[i][j] = fmaf(av[i], bv2[j], f[i][j]);
                }
            }
            #pragma unroll
            for (int i = 0; i < 4; ++i) {
                #pragma unroll
                for (int j = 0; j < 4; ++j)
                    sS[(ty * 4 + i) * SSS + tx + 16 * j] = f[i][j];
            }
        }
        __syncthreads();

        // softmax over k dim (scale applied here; exact softmax(scale*s))
        {
            const int wid = tid >> 5, lane = tid & 31;
            #pragma unroll
            for (int r = 0; r < 8; ++r) {
                const int t = wid * 8 + r;
                float v0 = sS[t * SSS + lane];
                float v1 = sS[t * SSS + 32 + lane];
                float m = fmaxf(v0, v1);
                #pragma unroll
                for (int o = 16; o > 0; o >>= 1)
                    m = fmaxf(m, __shfl_xor_sync(0xffffffffu, m, o));
                float e0 = __expf((v0 - m) * SCALE);
                float e1 = __expf((v1 - m) * SCALE);
                float s = e0 + e1;
                #pragma unroll
                for (int o = 16; o > 0; o >>= 1)
                    s += __shfl_xor_sync(0xffffffffu, s, o);
                const float inv = 1.0f / s;
                sS[t * SSS + lane]      = e0 * inv;
                sS[t * SSS + 32 + lane] = e1 * inv;
            }
        }
        __syncthreads();

        // o_h = P @ V  -> so[:, h*32 : h*32+32]
        {
            float f[4][2];
            #pragma unroll
            for (int i = 0; i < 4; ++i) { f[i][0] = 0.f; f[i][1] = 0.f; }
            #pragma unroll 4
            for (int k2 = 0; k2 < 64; ++k2) {
                float av[4];
                #pragma unroll
                for (int i = 0; i < 4; ++i) av[i] = sS[(ty * 4 + i) * SSS + k2];
                const float b0 = sv[k2 * QS + tx];
                const float b1 = sv[k2 * QS + tx + 16];
                #pragma unroll
                for (int i = 0; i < 4; ++i) {
                    f[i][0] = fmaf(av[i], b0, f[i][0]);
                    f[i][1] = fmaf(av[i], b1, f[i][1]);
                }
            }
            #pragma unroll
            for (int i = 0; i < 4; ++i) {
                so[(ty * 4 + i) * SXS + h * 32 + tx]      = f[i][0];
                so[(ty * 4 + i) * SXS + h * 32 + 16 + tx] = f[i][1];
            }
        }
        __syncthreads();
    }

    // ---------------- out projection: sx = so @ w_out^T + b_out ----------------
    for (int half = 0; half < 2; ++half) {
        const int co0 = half << 7;
        unsigned long long acc[8][4];
        #pragma unroll
        for (int i = 0; i < 8; ++i) {
            #pragma unroll
            for (int j = 0; j < 4; ++j) acc[i][j] = 0ull;
        }

        for (int kt = 0; kt < 4; ++kt) {
            const int kb = kt << 6;
            #pragma unroll
            for (int l = 0; l < 32; ++l) {
                int idx = tid + l * THREADS;
                int r = idx >> 6, kc = idx & 63;
                wsm[(r << 6) + ((((kc >> 2) ^ (r & 15)) << 2) | (kc & 3))] =
                    w_out[(co0 + r) * C + kb + kc];
            }
            __syncthreads();

            #pragma unroll 4
            for (int kk = 0; kk < 64; kk += 4) {
                ulonglong2 a[8];
                #pragma unroll
                for (int i = 0; i < 8; ++i)
                    a[i] = *(const ulonglong2*)(so + (typ * 8 + i) * SXS + kb + kk);
                const int sw = ((kk >> 2) ^ tx) << 2;
                ulonglong2 bv[4];
                #pragma unroll
                for (int j = 0; j < 4; ++j)
                    bv[j] = *(const ulonglong2*)(wsm + ((colg + 32 * j) << 6) + sw);
                #pragma unroll
                for (int i = 0; i < 8; ++i) {
                    #pragma unroll
                    for (int j = 0; j < 4; ++j) {
                        fma2(acc[i][j], a[i].x, bv[j].x);
                        fma2(acc[i][j], a[i].y, bv[j].y);
                    }
                }
            }
            __syncthreads();
        }

        #pragma unroll
        for (int j = 0; j < 4; ++j) {
            const int col = co0 + colg + 32 * j;
            const float bias = b_out[col];
            #pragma unroll
            for (int i = 0; i < 8; ++i) {
                unsigned long long A = acc[i][j];
                float lo = __uint_as_float((unsigned)A);
                float hi = __uint_as_float((unsigned)(A >> 32));
                sx[(typ * 8 + i) * SXS + col] = lo + hi + bias;
            }
        }
        __syncthreads();
    }

    // ---------------- LayerNorm over channels (per token) ----------------
    {
        const int wid = tid >> 5, lane = tid & 31;
        for (int r = 0; r < 8; ++r) {
            const int t = wid * 8 + r;
            float v[8];
            #pragma unroll
            for (int j = 0; j < 8; ++j) v[j] = sx[t * SXS + j * 32 + lane];
            float s = 0.f;
            #pragma unroll
            for (int j = 0; j < 8; ++j) s += v[j];
            #pragma unroll
            for (int o = 16; o > 0; o >>= 1) s += __shfl_xor_sync(0xffffffffu, s, o);
            const float mu = s * (1.0f / 256.0f);
            float q2 = 0.f;
            #pragma unroll
            for (int j = 0; j < 8; ++j) { float d = v[j] - mu; q2 = fmaf(d, d, q2); }
            #pragma unroll
            for (int o = 16; o > 0; o >>= 1) q2 += __shfl_xor_sync(0xffffffffu, q2, o);
            const float rs = rsqrtf(q2 * (1.0f / 256.0f) + 1e-5f);
            #pragma unroll
            for (int j = 0; j < 8; ++j) {
                const int c = j * 32 + lane;
                so[t * SXS + c] = (v[j] - mu) * rs * gamma[c] + beta[c];
            }
        }
    }
    __syncthreads();

    // ---------------- scatter to NCHW output ----------------
    float* ow = out + (size_t)bb * C * 65536 + (size_t)(hn * 8) * 256 + wn * 8;
    for (int idx = tid; idx < 64 * C; idx += THREADS) {
        int c = idx >> 6, t = idx & 63;
        ow[(size_t)c * 65536 + (t >> 3) * 256 + (t & 7)] = so[t * SXS + c];
    }
}

extern "C" void kernel_launch(void* const* d_in, const int* in_sizes, int n_in,
                              void* d_out, int out_size) {
    (void)in_sizes; (void)n_in; (void)out_size;
    const float* x     = (const float*)d_in[0];
    const float* w_in  = (const float*)d_in[1];
    const float* b_in  = (const float*)d_in[2];
    const float* w_out = (const float*)d_in[3];
    const float* b_out = (const float*)d_in[4];
    const float* gamma = (const float*)d_in[5];
    const float* beta  = (const float*)d_in[6];
    float* out = (float*)d_out;

    const int smem_bytes = (64 * 260 * 2 + 128 * 64 + 3 * 64 * 33 + 64 * 66) * 4; // 208128
    cudaFuncSetAttribute(lab_fused_kernel,
                         cudaFuncAttributeMaxDynamicSharedMemorySize, smem_bytes);
    lab_fused_kernel<<<4096, THREADS, smem_bytes>>>(x, w_in, b_in, w_out, b_out,
                                                    gamma, beta, out);
}